// round 8
// baseline (speedup 1.0000x reference)
#include <cuda_runtime.h>

#define DIM 768
#define NE 8
#define WARPS_PER_BLOCK 8
#define THREADS 256
// DIM/4 floats4 per token = 192 float4; 192/32 lanes = 6 float4 per lane
#define F4_PER_LANE 6

__global__ __launch_bounds__(THREADS, 4)
void router_kernel(const float* __restrict__ x,
                   const float* __restrict__ W,
                   const float* __restrict__ b,
                   float* __restrict__ out,
                   int n_tokens, int write_idx)
{
    __shared__ float Ws[NE * DIM];
    __shared__ float bs[NE];

    // Stage W (24 KB) + b into shared once per block, vectorized.
    {
        const float4* Wg = reinterpret_cast<const float4*>(W);
        float4* Wsm = reinterpret_cast<float4*>(Ws);
        #pragma unroll
        for (int i = threadIdx.x; i < NE * DIM / 4; i += THREADS)
            Wsm[i] = Wg[i];
        if (threadIdx.x < NE) bs[threadIdx.x] = b[threadIdx.x];
    }
    __syncthreads();

    const int warp = threadIdx.x >> 5;
    const int lane = threadIdx.x & 31;
    const int token = blockIdx.x * WARPS_PER_BLOCK + warp;
    if (token >= n_tokens) return;

    const float4* xp = reinterpret_cast<const float4*>(x + (size_t)token * DIM);

    float acc[NE];
    #pragma unroll
    for (int e = 0; e < NE; e++) acc[e] = 0.0f;

    // Streaming dot products: coalesced 128B/warp-phase loads, x read exactly once.
    #pragma unroll
    for (int i = 0; i < F4_PER_LANE; i++) {
        const float4 xv = xp[i * 32 + lane];
        #pragma unroll
        for (int e = 0; e < NE; e++) {
            const float4 wv =
                reinterpret_cast<const float4*>(Ws + e * DIM)[i * 32 + lane];
            acc[e] += xv.x * wv.x + xv.y * wv.y + xv.z * wv.z + xv.w * wv.w;
        }
    }

    // Butterfly reduce: afterwards every lane holds all 8 full logit sums.
    #pragma unroll
    for (int e = 0; e < NE; e++) {
        #pragma unroll
        for (int off = 16; off > 0; off >>= 1)
            acc[e] += __shfl_xor_sync(0xffffffffu, acc[e], off);
    }

    if (lane == 0) {
        float l[NE];
        float m = -1e30f;
        #pragma unroll
        for (int e = 0; e < NE; e++) {
            l[e] = acc[e] + bs[e];
            m = fmaxf(m, l[e]);
        }
        float denom = 0.0f;
        #pragma unroll
        for (int e = 0; e < NE; e++) {
            l[e] = __expf(l[e] - m);
            denom += l[e];
        }
        // top-2 on exp-values (monotone => same order as gates / logits).
        // Strict '>' keeps lowest index on ties, matching jax.lax.top_k.
        int i1 = 0; float v1 = l[0];
        #pragma unroll
        for (int e = 1; e < NE; e++)
            if (l[e] > v1) { v1 = l[e]; i1 = e; }
        int i2 = -1; float v2 = -1.0f;
        #pragma unroll
        for (int e = 0; e < NE; e++)
            if (e != i1 && l[e] > v2) { v2 = l[e]; i2 = e; }

        const float inv = 1.0f / denom;
        out[(size_t)token * 2 + 0] = v1 * inv;
        out[(size_t)token * 2 + 1] = v2 * inv;
        if (write_idx) {
            float* oi = out + (size_t)n_tokens * 2;
            oi[(size_t)token * 2 + 0] = (float)i1;   // float(int) exact
            oi[(size_t)token * 2 + 1] = (float)i2;
        }
    }
}

extern "C" void kernel_launch(void* const* d_in, const int* in_sizes, int n_in,
                              void* d_out, int out_size) {
    const float* x = (const float*)d_in[0];  // [128,197,768]
    const float* W = (const float*)d_in[1];  // [8,768]
    const float* b = (const float*)d_in[2];  // [8]
    float* out = (float*)d_out;

    const int n_tokens = in_sizes[0] / DIM;            // 25216
    const int write_idx = (out_size >= 4 * n_tokens);  // tuple packed: gates then idx

    const int grid = (n_tokens + WARPS_PER_BLOCK - 1) / WARPS_PER_BLOCK;
    router_kernel<<<grid, THREADS>>>(x, W, b, out, n_tokens, write_idx);
}

// round 10
// speedup vs baseline: 1.3441x; 1.3441x over previous
#include <cuda_runtime.h>

#define DIM 768
#define NE 8
#define WARPS_PER_BLOCK 8
#define THREADS 256
#define TOK_PER_WARP 4
// DIM/4 = 192 float4 per token row; 192/32 lanes = 6 float4 per lane
#define F4_PER_LANE 6

__global__ __launch_bounds__(THREADS, 2)
void router_kernel(const float* __restrict__ x,
                   const float* __restrict__ W,
                   const float* __restrict__ b,
                   float* __restrict__ out,
                   int n_tokens, int write_idx)
{
    __shared__ float Ws[NE * DIM];
    __shared__ float bs[NE];

    // Stage W (24 KB) + b into shared once per block, vectorized.
    {
        const float4* Wg = reinterpret_cast<const float4*>(W);
        float4* Wsm = reinterpret_cast<float4*>(Ws);
        #pragma unroll
        for (int i = threadIdx.x; i < NE * DIM / 4; i += THREADS)
            Wsm[i] = Wg[i];
        if (threadIdx.x < NE) bs[threadIdx.x] = b[threadIdx.x];
    }
    __syncthreads();

    const int warp = threadIdx.x >> 5;
    const int lane = threadIdx.x & 31;
    const int token0 = (blockIdx.x * WARPS_PER_BLOCK + warp) * TOK_PER_WARP;
    if (token0 >= n_tokens) return;

    // For n_tokens = 25216 (divisible by 32) every warp's 4 tokens are
    // in-bounds; keep one block-level flag so the hot loop has no guards.
    const bool full = (token0 + TOK_PER_WARP <= n_tokens);

    const float4* xp = reinterpret_cast<const float4*>(x) +
                       (size_t)token0 * (DIM / 4);

    float acc[TOK_PER_WARP][NE];
    #pragma unroll
    for (int t = 0; t < TOK_PER_WARP; t++)
        #pragma unroll
        for (int e = 0; e < NE; e++) acc[t][e] = 0.0f;

    // Each W shared-read amortized over TOK_PER_WARP tokens:
    // per i: 4 independent coalesced LDG.128 (x stream), 8 LDS.128 (W),
    // 32 float4-dot FMAs. LDS traffic = 1/4 of 1-token-per-warp layout.
    #pragma unroll
    for (int i = 0; i < F4_PER_LANE; i++) {
        float4 xv[TOK_PER_WARP];
        #pragma unroll
        for (int t = 0; t < TOK_PER_WARP; t++) {
            if (full || token0 + t < n_tokens)
                xv[t] = xp[(size_t)t * (DIM / 4) + i * 32 + lane];
            else
                xv[t] = make_float4(0.f, 0.f, 0.f, 0.f);
        }
        #pragma unroll
        for (int e = 0; e < NE; e++) {
            const float4 wv =
                reinterpret_cast<const float4*>(Ws + e * DIM)[i * 32 + lane];
            #pragma unroll
            for (int t = 0; t < TOK_PER_WARP; t++)
                acc[t][e] += xv[t].x * wv.x + xv[t].y * wv.y +
                             xv[t].z * wv.z + xv[t].w * wv.w;
        }
    }

    // Butterfly reduce: every lane ends up with all 32 full sums.
    #pragma unroll
    for (int t = 0; t < TOK_PER_WARP; t++)
        #pragma unroll
        for (int e = 0; e < NE; e++)
            #pragma unroll
            for (int off = 16; off > 0; off >>= 1)
                acc[t][e] += __shfl_xor_sync(0xffffffffu, acc[t][e], off);

    // Epilogue: lane t finishes token t (compile-time unrolled so acc
    // indices stay static -> no local-memory spill).
    #pragma unroll
    for (int t = 0; t < TOK_PER_WARP; t++) {
        if (lane == t && token0 + t < n_tokens) {
            const int token = token0 + t;
            float l[NE];
            float m = -1e30f;
            #pragma unroll
            for (int e = 0; e < NE; e++) {
                l[e] = acc[t][e] + bs[e];
                m = fmaxf(m, l[e]);
            }
            float denom = 0.0f;
            #pragma unroll
            for (int e = 0; e < NE; e++) {
                l[e] = __expf(l[e] - m);
                denom += l[e];
            }
            // top-2 on exp-values (monotone => same order as gates).
            // Strict '>' keeps lowest index on ties, matching jax.lax.top_k.
            int i1 = 0; float v1 = l[0];
            #pragma unroll
            for (int e = 1; e < NE; e++)
                if (l[e] > v1) { v1 = l[e]; i1 = e; }
            int i2 = -1; float v2 = -1.0f;
            #pragma unroll
            for (int e = 0; e < NE; e++)
                if (e != i1 && l[e] > v2) { v2 = l[e]; i2 = e; }

            const float inv = 1.0f / denom;
            out[(size_t)token * 2 + 0] = v1 * inv;
            out[(size_t)token * 2 + 1] = v2 * inv;
            if (write_idx) {
                float* oi = out + (size_t)n_tokens * 2;
                oi[(size_t)token * 2 + 0] = (float)i1;   // float(int) exact
                oi[(size_t)token * 2 + 1] = (float)i2;
            }
        }
    }
}

extern "C" void kernel_launch(void* const* d_in, const int* in_sizes, int n_in,
                              void* d_out, int out_size) {
    const float* x = (const float*)d_in[0];  // [128,197,768]
    const float* W = (const float*)d_in[1];  // [8,768]
    const float* b = (const float*)d_in[2];  // [8]
    float* out = (float*)d_out;

    const int n_tokens = in_sizes[0] / DIM;            // 25216
    const int write_idx = (out_size >= 4 * n_tokens);  // tuple packed: gates then idx

    const int tok_per_block = WARPS_PER_BLOCK * TOK_PER_WARP;
    const int grid = (n_tokens + tok_per_block - 1) / tok_per_block;
    router_kernel<<<grid, THREADS>>>(x, W, b, out, n_tokens, write_idx);
}

// round 13
// speedup vs baseline: 1.7610x; 1.3102x over previous
#include <cuda_runtime.h>

#define DIM 768
#define NE 8
#define WARPS_PER_BLOCK 8
#define THREADS 256
#define TOK_PER_WARP 4
// DIM/4 = 192 float4 per token row; 192/32 lanes = 6 float4 per lane
#define F4_PER_LANE 6

__global__ __launch_bounds__(THREADS, 3)
void router_kernel(const float* __restrict__ x,
                   const float* __restrict__ W,
                   const float* __restrict__ b,
                   float* __restrict__ out,
                   int n_tokens, int write_idx)
{
    __shared__ float Ws[NE * DIM];
    __shared__ float bs[NE];

    // Stage W (24 KB) + b into shared once per block, vectorized.
    {
        const float4* Wg = reinterpret_cast<const float4*>(W);
        float4* Wsm = reinterpret_cast<float4*>(Ws);
        #pragma unroll
        for (int i = threadIdx.x; i < NE * DIM / 4; i += THREADS)
            Wsm[i] = Wg[i];
        if (threadIdx.x < NE) bs[threadIdx.x] = b[threadIdx.x];
    }
    __syncthreads();

    const int warp = threadIdx.x >> 5;
    const int lane = threadIdx.x & 31;
    const int token0 = (blockIdx.x * WARPS_PER_BLOCK + warp) * TOK_PER_WARP;
    if (token0 >= n_tokens) return;

    // Per-token base pointers, clamped (25216 % 32 == 0 so clamp is a no-op
    // on this shape; keeps other shapes memory-safe without hot-loop guards).
    const float4* xp[TOK_PER_WARP];
    #pragma unroll
    for (int t = 0; t < TOK_PER_WARP; t++) {
        int tok = token0 + t;
        if (tok > n_tokens - 1) tok = n_tokens - 1;
        xp[t] = reinterpret_cast<const float4*>(x) + (size_t)tok * (DIM / 4) + lane;
    }

    // Flat accumulators: v[t*8 + e]. After the transpose-reduce below,
    // lane L holds the full sum of v[L].
    float v[TOK_PER_WARP * NE];
    #pragma unroll
    for (int j = 0; j < TOK_PER_WARP * NE; j++) v[j] = 0.0f;

    // Mainloop: per i, 4 independent coalesced LDG.128 (x stream) and
    // 8 LDS.128 (W, amortized over 4 tokens), 32 float4-dots.
    #pragma unroll
    for (int i = 0; i < F4_PER_LANE; i++) {
        float4 xv[TOK_PER_WARP];
        #pragma unroll
        for (int t = 0; t < TOK_PER_WARP; t++)
            xv[t] = xp[t][i * 32];
        #pragma unroll
        for (int e = 0; e < NE; e++) {
            const float4 wv =
                reinterpret_cast<const float4*>(Ws + e * DIM)[i * 32 + lane];
            #pragma unroll
            for (int t = 0; t < TOK_PER_WARP; t++)
                v[t * NE + e] += xv[t].x * wv.x + xv[t].y * wv.y +
                                 xv[t].z * wv.z + xv[t].w * wv.w;
        }
    }

    // Warp transpose-reduce: 32 values -> 32 lanes in 31 shuffles.
    // After step `off`, lanes keep `off` partials; final: lane L = sum(v[L]).
    #pragma unroll
    for (int off = 16; off > 0; off >>= 1) {
        #pragma unroll
        for (int j = 0; j < off; j++) {
            const bool hi = (lane & off) != 0;
            float send = hi ? v[j] : v[j + off];
            float other = __shfl_xor_sync(0xffffffffu, send, off);
            v[j] = (hi ? v[j + off] : v[j]) + other;
        }
    }

    // Lane L owns logit for token t = L>>3, expert e = L&7.
    const int t = lane >> 3;
    const int e = lane & 7;
    const int token = token0 + t;

    float logit = v[0] + bs[e];

    // Softmax over the 8-lane expert group (3+3 shuffles).
    float m = logit;
    #pragma unroll
    for (int off = 4; off > 0; off >>= 1)
        m = fmaxf(m, __shfl_xor_sync(0xffffffffu, m, off));
    float ex = __expf(logit - m);
    float s = ex;
    #pragma unroll
    for (int off = 4; off > 0; off >>= 1)
        s += __shfl_xor_sync(0xffffffffu, s, off);
    const float gate = ex / s;

    // Top-1 with lowest-index tie-break (matches jax.lax.top_k).
    float bv = gate; int bi = e;
    #pragma unroll
    for (int off = 4; off > 0; off >>= 1) {
        float ov = __shfl_xor_sync(0xffffffffu, bv, off);
        int   oi = __shfl_xor_sync(0xffffffffu, bi, off);
        if (ov > bv || (ov == bv && oi < bi)) { bv = ov; bi = oi; }
    }
    // Top-2: exclude the winner (gates > 0, so -1 is a safe sentinel).
    float cv = (e == bi) ? -1.0f : gate; int ci = e;
    #pragma unroll
    for (int off = 4; off > 0; off >>= 1) {
        float ov = __shfl_xor_sync(0xffffffffu, cv, off);
        int   oi = __shfl_xor_sync(0xffffffffu, ci, off);
        if (ov > cv || (ov == cv && oi < ci)) { cv = ov; ci = oi; }
    }

    // One writer lane per token group.
    if (e == 0 && token < n_tokens) {
        out[(size_t)token * 2 + 0] = bv;
        out[(size_t)token * 2 + 1] = cv;
        if (write_idx) {
            float* oi = out + (size_t)n_tokens * 2;
            oi[(size_t)token * 2 + 0] = (float)bi;   // float(int) exact
            oi[(size_t)token * 2 + 1] = (float)ci;
        }
    }
}

extern "C" void kernel_launch(void* const* d_in, const int* in_sizes, int n_in,
                              void* d_out, int out_size) {
    const float* x = (const float*)d_in[0];  // [128,197,768]
    const float* W = (const float*)d_in[1];  // [8,768]
    const float* b = (const float*)d_in[2];  // [8]
    float* out = (float*)d_out;

    const int n_tokens = in_sizes[0] / DIM;            // 25216
    const int write_idx = (out_size >= 4 * n_tokens);  // tuple packed: gates then idx

    const int tok_per_block = WARPS_PER_BLOCK * TOK_PER_WARP;
    const int grid = (n_tokens + tok_per_block - 1) / tok_per_block;
    router_kernel<<<grid, THREADS>>>(x, W, b, out, n_tokens, write_idx);
}